// round 1
// baseline (speedup 1.0000x reference)
#include <cuda_runtime.h>
#include <cuda_bf16.h>
#include <math.h>

// Problem constants
#define LL 13
#define HH 48
#define WW 96
#define DD 512
#define TT (LL*HH*WW)        // 59904 tokens
#define NHEAD 16
#define HD 32

// Scratch (device globals; no cudaMalloc allowed)
__device__ float g_ln[(size_t)TT * DD];
__device__ float g_qkv[(size_t)TT * 3 * DD];
__device__ float g_att[(size_t)TT * DD];
__device__ float g_state[(size_t)TT * DD];
__device__ float g_sin_lat[HH * 16];
__device__ float g_cos_lat[HH * 16];
__device__ float g_sin_lon[WW * 16];
__device__ float g_cos_lon[WW * 16];

// ---------------------------------------------------------------------------
// Rotary sin/cos precompute. mode 0: lat axis (lon=0), mode 1: lon axis (lat=0)
// ---------------------------------------------------------------------------
__global__ void rotary_kernel(const float* __restrict__ grid, int S, int mode,
                              float* __restrict__ sout, float* __restrict__ cout)
{
    int idx = blockIdx.x * blockDim.x + threadIdx.x;
    if (idx >= S * 16) return;
    int s = idx >> 4;
    int f = idx & 15;
    const float PI = 3.14159265358979323846f;
    float lat, lon;
    if (mode == 0) { lat = grid[s]; lon = 0.f; }
    else           { lat = 0.f;     lon = grid[s]; }
    float two_pi = 2.f * PI;
    float r = fmodf(lon + PI, two_pi);
    if (r < 0.f) r += two_pi;
    float lonw = r - PI;
    float lo = -(PI * 0.5f) + 1e-6f;
    float hi =  (PI * 0.5f) - 1e-6f;
    float latc = fminf(fmaxf(lat, lo), hi);
    float invf = powf(10000.f, -(float)f / 16.f);
    float phase = (latc + lonw * cosf(latc)) * invf;
    sout[idx] = sinf(phase);
    cout[idx] = cosf(phase);
}

// ---------------------------------------------------------------------------
// LayerNorm over D=512 per token. 128 threads/block, one block per token.
// ---------------------------------------------------------------------------
__global__ void ln_kernel(const float* __restrict__ x, const float* __restrict__ g,
                          const float* __restrict__ b, float* __restrict__ out)
{
    __shared__ float red[8];
    int t = blockIdx.x;
    int tid = threadIdx.x;
    const float* row = x + (size_t)t * DD;
    float4 v = *(const float4*)(row + tid * 4);
    float s = v.x + v.y + v.z + v.w;
    float q = v.x*v.x + v.y*v.y + v.z*v.z + v.w*v.w;
    #pragma unroll
    for (int o = 16; o; o >>= 1) {
        s += __shfl_xor_sync(0xffffffffu, s, o);
        q += __shfl_xor_sync(0xffffffffu, q, o);
    }
    int lane = tid & 31, w = tid >> 5;
    if (lane == 0) { red[w] = s; red[4 + w] = q; }
    __syncthreads();
    if (tid == 0) {
        red[0] = red[0] + red[1] + red[2] + red[3];
        red[4] = red[4] + red[5] + red[6] + red[7];
    }
    __syncthreads();
    float mean = red[0] * (1.f / 512.f);
    float var  = red[4] * (1.f / 512.f) - mean * mean;
    float inv = rsqrtf(var + 1e-5f);
    float4 gv = *(const float4*)(g + tid * 4);
    float4 bv = *(const float4*)(b + tid * 4);
    float4 o;
    o.x = (v.x - mean) * inv * gv.x + bv.x;
    o.y = (v.y - mean) * inv * gv.y + bv.y;
    o.z = (v.z - mean) * inv * gv.z + bv.z;
    o.w = (v.w - mean) * inv * gv.w + bv.w;
    *(float4*)(out + (size_t)t * DD + tid * 4) = o;
}

// ---------------------------------------------------------------------------
// SGEMM: C[M,N] = A[M,K] @ B[K,N] + bias[N] (+ res[M,N]).
// 128x128 tile, BK=8, 256 threads, 8x8 per-thread microtile.
// M,N,K all multiples of tile dims in this problem (no predication).
// ---------------------------------------------------------------------------
__global__ __launch_bounds__(256) void sgemm_kernel(
    const float* __restrict__ A, const float* __restrict__ B,
    const float* __restrict__ bias, const float* __restrict__ res,
    float* __restrict__ C, int M, int N, int K)
{
    __shared__ float As[8][128];
    __shared__ float Bs[8][128];
    int tid = threadIdx.x;
    int m0 = blockIdx.y * 128;
    int n0 = blockIdx.x * 128;

    int ar = tid >> 1;            // 0..127  (row within A tile)
    int ak = (tid & 1) * 4;       // 0 or 4  (k-offset within A tile)
    int bk = tid >> 5;            // 0..7    (row within B tile)
    int bc = (tid & 31) * 4;      // col within B tile
    int tx = tid & 15;
    int ty = tid >> 4;

    const float* Aptr = A + (size_t)(m0 + ar) * K + ak;
    const float* Bptr = B + (size_t)bk * N + n0 + bc;

    float acc[8][8];
    #pragma unroll
    for (int i = 0; i < 8; i++)
        #pragma unroll
        for (int j = 0; j < 8; j++) acc[i][j] = 0.f;

    for (int k0 = 0; k0 < K; k0 += 8) {
        float4 av = *(const float4*)(Aptr + k0);
        float4 bv = *(const float4*)(Bptr + (size_t)k0 * N);
        As[ak + 0][ar] = av.x;
        As[ak + 1][ar] = av.y;
        As[ak + 2][ar] = av.z;
        As[ak + 3][ar] = av.w;
        *(float4*)&Bs[bk][bc] = bv;
        __syncthreads();
        #pragma unroll
        for (int kk = 0; kk < 8; kk++) {
            float a[8], bb[8];
            *(float4*)(a)     = *(const float4*)&As[kk][ty * 4];
            *(float4*)(a + 4) = *(const float4*)&As[kk][64 + ty * 4];
            *(float4*)(bb)     = *(const float4*)&Bs[kk][tx * 4];
            *(float4*)(bb + 4) = *(const float4*)&Bs[kk][64 + tx * 4];
            #pragma unroll
            for (int i = 0; i < 8; i++)
                #pragma unroll
                for (int j = 0; j < 8; j++)
                    acc[i][j] += a[i] * bb[j];
        }
        __syncthreads();
    }

    #pragma unroll
    for (int i = 0; i < 8; i++) {
        int row = m0 + ((i < 4) ? (ty * 4 + i) : (64 + ty * 4 + i - 4));
        #pragma unroll
        for (int j = 0; j < 8; j++) {
            int col = n0 + ((j < 4) ? (tx * 4 + j) : (64 + tx * 4 + j - 4));
            float v = acc[i][j] + bias[col];
            if (res) v += res[(size_t)row * N + col];
            C[(size_t)row * N + col] = v;
        }
    }
}

// ---------------------------------------------------------------------------
// Attention per (sequence n, head h). flat(n,s) = cd*(n/d0) + cm*(n%d0) + cs*s
// rsin/rcos: [S][16] rotary tables (nullptr -> no rotary, lev axis).
// 128 threads (4 warps). Each warp processes q positions warp, warp+4, ...
// ---------------------------------------------------------------------------
__global__ __launch_bounds__(128) void attn_kernel(
    const float* __restrict__ qkv, float* __restrict__ att,
    const float* __restrict__ rsin, const float* __restrict__ rcos,
    int S, int d0, int cd, int cm, int cs)
{
    __shared__ float k_s[96][33];
    __shared__ float v_s[96][33];
    __shared__ float probs[4][96];

    int n = blockIdx.x;
    int h = blockIdx.y;
    int tid = threadIdx.x;
    int lane = tid & 31;
    int warp = tid >> 5;

    int nb = cd * (n / d0) + cm * (n % d0);
    int qoff = h * HD;
    int koff = DD + h * HD;
    int voff = 2 * DD + h * HD;

    // Stage K (rotated) and V into shared memory
    for (int idx = tid; idx < S * 32; idx += 128) {
        int j = idx >> 5;
        int d = idx & 31;
        size_t rowbase = (size_t)(nb + cs * j) * (3 * DD);
        float kv;
        if (rsin) {
            int i = d & 15;
            float sn = rsin[j * 16 + i], cs_ = rcos[j * 16 + i];
            float x1 = qkv[rowbase + koff + 2 * i];
            float x2 = qkv[rowbase + koff + 2 * i + 1];
            kv = (d < 16) ? (x1 * cs_ - x2 * sn) : (x1 * sn + x2 * cs_);
        } else {
            kv = qkv[rowbase + koff + d];
        }
        k_s[j][d] = kv;
        v_s[j][d] = qkv[rowbase + voff + d];
    }
    __syncthreads();

    const float scale = 0.17677669529663687f; // 1/sqrt(32)

    for (int sq = warp; sq < S; sq += 4) {
        size_t qrow = (size_t)(nb + cs * sq) * (3 * DD) + qoff;
        float q[32];
        if (rsin) {
            #pragma unroll
            for (int i = 0; i < 16; i++) {
                float sn = rsin[sq * 16 + i], cs_ = rcos[sq * 16 + i];
                float x1 = qkv[qrow + 2 * i];
                float x2 = qkv[qrow + 2 * i + 1];
                q[i]      = x1 * cs_ - x2 * sn;
                q[16 + i] = x1 * sn + x2 * cs_;
            }
        } else {
            #pragma unroll
            for (int i = 0; i < 32; i++) q[i] = qkv[qrow + i];
        }

        // Scores: lane handles keys lane, lane+32, lane+64
        float sc[3];
        float mx = -1e30f;
        #pragma unroll
        for (int kb = 0; kb < 3; kb++) {
            int j = lane + kb * 32;
            float a = 0.f;
            if (j < S) {
                #pragma unroll
                for (int d = 0; d < 32; d++) a += q[d] * k_s[j][d];
                a *= scale;
                mx = fmaxf(mx, a);
            }
            sc[kb] = a;
        }
        #pragma unroll
        for (int o = 16; o; o >>= 1) mx = fmaxf(mx, __shfl_xor_sync(0xffffffffu, mx, o));

        float sum = 0.f;
        #pragma unroll
        for (int kb = 0; kb < 3; kb++) {
            int j = lane + kb * 32;
            if (j < S) {
                float e = expf(sc[kb] - mx);
                probs[warp][j] = e;
                sum += e;
            }
        }
        #pragma unroll
        for (int o = 16; o; o >>= 1) sum += __shfl_xor_sync(0xffffffffu, sum, o);
        float rinv = 1.f / sum;

        __syncwarp();
        // Output: lane = head dim
        float o = 0.f;
        for (int j = 0; j < S; j++) o += probs[warp][j] * v_s[j][lane];
        o *= rinv;
        att[(size_t)(nb + cs * sq) * DD + h * HD + lane] = o;
        __syncwarp();
    }
}

// ---------------------------------------------------------------------------
// Host launcher
// ---------------------------------------------------------------------------
extern "C" void kernel_launch(void* const* d_in, const int* in_sizes, int n_in,
                              void* d_out, int out_size)
{
    const float* x         = (const float*)d_in[0];
    const float* lat_grid  = (const float*)d_in[1];
    const float* lon_grid  = (const float*)d_in[2];
    const float* lat_qkv_w = (const float*)d_in[3];
    const float* lat_qkv_b = (const float*)d_in[4];
    const float* lon_qkv_w = (const float*)d_in[5];
    const float* lon_qkv_b = (const float*)d_in[6];
    const float* lev_qkv_w = (const float*)d_in[7];
    const float* lev_qkv_b = (const float*)d_in[8];
    const float* proj_w    = (const float*)d_in[9];
    const float* proj_b    = (const float*)d_in[10];
    const float* g_lat     = (const float*)d_in[11];
    const float* b_lat     = (const float*)d_in[12];
    const float* g_lon     = (const float*)d_in[13];
    const float* b_lon     = (const float*)d_in[14];
    const float* g_lev     = (const float*)d_in[15];
    const float* b_lev     = (const float*)d_in[16];
    float* out = (float*)d_out;

    float *ln, *qkv, *attb, *state, *slat, *clat, *slon, *clon;
    cudaGetSymbolAddress((void**)&ln,    g_ln);
    cudaGetSymbolAddress((void**)&qkv,   g_qkv);
    cudaGetSymbolAddress((void**)&attb,  g_att);
    cudaGetSymbolAddress((void**)&state, g_state);
    cudaGetSymbolAddress((void**)&slat,  g_sin_lat);
    cudaGetSymbolAddress((void**)&clat,  g_cos_lat);
    cudaGetSymbolAddress((void**)&slon,  g_sin_lon);
    cudaGetSymbolAddress((void**)&clon,  g_cos_lon);

    rotary_kernel<<<(HH * 16 + 127) / 128, 128>>>(lat_grid, HH, 0, slat, clat);
    rotary_kernel<<<(WW * 16 + 127) / 128, 128>>>(lon_grid, WW, 1, slon, clon);

    dim3 gq(3 * DD / 128, TT / 128);   // QKV gemm grid (12, 468)
    dim3 gp(DD / 128, TT / 128);       // proj gemm grid (4, 468)

    // ---- lat block (seq = H, n over (l,w)) ----
    ln_kernel<<<TT, 128>>>(x, g_lat, b_lat, ln);
    sgemm_kernel<<<gq, 256>>>(ln, lat_qkv_w, lat_qkv_b, nullptr, qkv, TT, 3 * DD, DD);
    attn_kernel<<<dim3(LL * WW, NHEAD), 128>>>(qkv, attb, slat, clat,
                                               HH, WW, HH * WW, 1, WW);
    sgemm_kernel<<<gp, 256>>>(attb, proj_w, proj_b, x, state, TT, DD, DD);

    // ---- lon block (seq = W, n over (l,h)) ----
    ln_kernel<<<TT, 128>>>(state, g_lon, b_lon, ln);
    sgemm_kernel<<<gq, 256>>>(ln, lon_qkv_w, lon_qkv_b, nullptr, qkv, TT, 3 * DD, DD);
    attn_kernel<<<dim3(LL * HH, NHEAD), 128>>>(qkv, attb, slon, clon,
                                               WW, 1, WW, 0, 1);
    sgemm_kernel<<<gp, 256>>>(attb, proj_w, proj_b, state, state, TT, DD, DD);

    // ---- lev block (seq = L, n over (h,w), no rotary) ----
    ln_kernel<<<TT, 128>>>(state, g_lev, b_lev, ln);
    sgemm_kernel<<<gq, 256>>>(ln, lev_qkv_w, lev_qkv_b, nullptr, qkv, TT, 3 * DD, DD);
    attn_kernel<<<dim3(HH * WW, NHEAD), 128>>>(qkv, attb, nullptr, nullptr,
                                               LL, 1, 1, 0, HH * WW);
    sgemm_kernel<<<gp, 256>>>(attb, proj_w, proj_b, state, out, TT, DD, DD);
}

// round 2
// speedup vs baseline: 1.9106x; 1.9106x over previous
#include <cuda_runtime.h>
#include <cuda_bf16.h>
#include <math.h>
#include <stdint.h>

// Problem constants
#define LL 13
#define HH 48
#define WW 96
#define DD 512
#define TT (LL*HH*WW)        // 59904 tokens
#define NHEAD 16
#define HD 32

// Scratch (device globals; no cudaMalloc allowed)
__device__ float g_ln[(size_t)TT * DD];
__device__ float g_qkv[(size_t)TT * 3 * DD];
__device__ float g_att[(size_t)TT * DD];
__device__ float g_state[(size_t)TT * DD];
__device__ float g_sin_lat[HH * 16];
__device__ float g_cos_lat[HH * 16];
__device__ float g_sin_lon[WW * 16];
__device__ float g_cos_lon[WW * 16];

// ---------------------------------------------------------------------------
// Rotary sin/cos precompute. mode 0: lat axis (lon=0), mode 1: lon axis (lat=0)
// ---------------------------------------------------------------------------
__global__ void rotary_kernel(const float* __restrict__ grid, int S, int mode,
                              float* __restrict__ sout, float* __restrict__ cout)
{
    int idx = blockIdx.x * blockDim.x + threadIdx.x;
    if (idx >= S * 16) return;
    int s = idx >> 4;
    int f = idx & 15;
    const float PI = 3.14159265358979323846f;
    float lat, lon;
    if (mode == 0) { lat = grid[s]; lon = 0.f; }
    else           { lat = 0.f;     lon = grid[s]; }
    float two_pi = 2.f * PI;
    float r = fmodf(lon + PI, two_pi);
    if (r < 0.f) r += two_pi;
    float lonw = r - PI;
    float lo = -(PI * 0.5f) + 1e-6f;
    float hi =  (PI * 0.5f) - 1e-6f;
    float latc = fminf(fmaxf(lat, lo), hi);
    float invf = powf(10000.f, -(float)f / 16.f);
    float phase = (latc + lonw * cosf(latc)) * invf;
    sout[idx] = sinf(phase);
    cout[idx] = cosf(phase);
}

// ---------------------------------------------------------------------------
// LayerNorm over D=512 per token. 128 threads/block, one block per token.
// ---------------------------------------------------------------------------
__global__ void ln_kernel(const float* __restrict__ x, const float* __restrict__ g,
                          const float* __restrict__ b, float* __restrict__ out)
{
    __shared__ float red[8];
    int t = blockIdx.x;
    int tid = threadIdx.x;
    const float* row = x + (size_t)t * DD;
    float4 v = *(const float4*)(row + tid * 4);
    float s = v.x + v.y + v.z + v.w;
    float q = v.x*v.x + v.y*v.y + v.z*v.z + v.w*v.w;
    #pragma unroll
    for (int o = 16; o; o >>= 1) {
        s += __shfl_xor_sync(0xffffffffu, s, o);
        q += __shfl_xor_sync(0xffffffffu, q, o);
    }
    int lane = tid & 31, w = tid >> 5;
    if (lane == 0) { red[w] = s; red[4 + w] = q; }
    __syncthreads();
    if (tid == 0) {
        red[0] = red[0] + red[1] + red[2] + red[3];
        red[4] = red[4] + red[5] + red[6] + red[7];
    }
    __syncthreads();
    float mean = red[0] * (1.f / 512.f);
    float var  = red[4] * (1.f / 512.f) - mean * mean;
    float inv = rsqrtf(var + 1e-5f);
    float4 gv = *(const float4*)(g + tid * 4);
    float4 bv = *(const float4*)(b + tid * 4);
    float4 o;
    o.x = (v.x - mean) * inv * gv.x + bv.x;
    o.y = (v.y - mean) * inv * gv.y + bv.y;
    o.z = (v.z - mean) * inv * gv.z + bv.z;
    o.w = (v.w - mean) * inv * gv.w + bv.w;
    *(float4*)(out + (size_t)t * DD + tid * 4) = o;
}

// ---------------------------------------------------------------------------
// TF32 tensor-core GEMM: C[M,N] = A[M,K] @ B[K,N] + bias[N] (+ res[M,N])
// Block tile 128x128, BK=16, 256 threads = 8 warps (2x4), warp tile 64x32.
// mma.sync.aligned.m16n8k8.row.col.f32.tf32.tf32.f32
// Shared layouts padded for conflict-free 32-bit fragment loads:
//   As[128][20]  (banks 20g+c mod 32 -> all 32 distinct)
//   Bs[16][136]  (banks 8c+g  mod 32 -> all 32 distinct)
// ---------------------------------------------------------------------------
__device__ __forceinline__ void mma_tf32(float* d, const uint32_t* a, const uint32_t* b)
{
    asm volatile(
        "mma.sync.aligned.m16n8k8.row.col.f32.tf32.tf32.f32 "
        "{%0,%1,%2,%3}, {%4,%5,%6,%7}, {%8,%9}, {%0,%1,%2,%3};"
        : "+f"(d[0]), "+f"(d[1]), "+f"(d[2]), "+f"(d[3])
        : "r"(a[0]), "r"(a[1]), "r"(a[2]), "r"(a[3]), "r"(b[0]), "r"(b[1]));
}

__global__ __launch_bounds__(256) void gemm_tc_kernel(
    const float* __restrict__ A, const float* __restrict__ B,
    const float* __restrict__ bias, const float* __restrict__ res,
    float* __restrict__ C, int M, int N, int K)
{
    __shared__ float As[128][20];
    __shared__ float Bs[16][136];

    int tid  = threadIdx.x;
    int lane = tid & 31;
    int warp = tid >> 5;
    int wm   = warp >> 2;     // 0..1 -> 64 rows each
    int wn   = warp & 3;      // 0..3 -> 32 cols each
    int r    = lane >> 2;     // fragment group id
    int c    = lane & 3;      // fragment thread-in-group

    int m0 = blockIdx.y * 128;
    int n0 = blockIdx.x * 128;

    // Global load mapping
    int aRow = tid >> 2;           // 0..63  (and +64)
    int aCol = (tid & 3) * 4;      // 0,4,8,12
    int bK   = tid >> 5;           // 0..7   (and +8)
    int bCol = (tid & 31) * 4;

    const float* Aptr = A + (size_t)(m0 + aRow) * K + aCol;
    const float* Bptr = B + (size_t)bK * N + n0 + bCol;

    float acc[4][4][4];
    #pragma unroll
    for (int i = 0; i < 4; i++)
        #pragma unroll
        for (int j = 0; j < 4; j++)
            #pragma unroll
            for (int e = 0; e < 4; e++) acc[i][j][e] = 0.f;

    // Prefetch chunk 0
    float4 a0v = *(const float4*)(Aptr);
    float4 a1v = *(const float4*)(Aptr + (size_t)64 * K);
    float4 b0v = *(const float4*)(Bptr);
    float4 b1v = *(const float4*)(Bptr + (size_t)8 * N);

    const int NCHUNK = K / 16;
    for (int chunk = 0; chunk < NCHUNK; chunk++) {
        // Store staged regs to smem
        *(float4*)&As[aRow][aCol]      = a0v;
        *(float4*)&As[aRow + 64][aCol] = a1v;
        *(float4*)&Bs[bK][bCol]        = b0v;
        *(float4*)&Bs[bK + 8][bCol]    = b1v;
        __syncthreads();

        // Prefetch next chunk while computing
        if (chunk + 1 < NCHUNK) {
            int k0 = (chunk + 1) * 16;
            a0v = *(const float4*)(Aptr + k0);
            a1v = *(const float4*)(Aptr + (size_t)64 * K + k0);
            b0v = *(const float4*)(Bptr + (size_t)k0 * N);
            b1v = *(const float4*)(Bptr + (size_t)(k0 + 8) * N);
        }

        #pragma unroll
        for (int ks = 0; ks < 2; ks++) {
            int kb = ks * 8;
            uint32_t afrag[4][4];
            #pragma unroll
            for (int i = 0; i < 4; i++) {
                int row = wm * 64 + i * 16 + r;
                afrag[i][0] = __float_as_uint(As[row][kb + c]);
                afrag[i][1] = __float_as_uint(As[row + 8][kb + c]);
                afrag[i][2] = __float_as_uint(As[row][kb + c + 4]);
                afrag[i][3] = __float_as_uint(As[row + 8][kb + c + 4]);
            }
            uint32_t bfrag[4][2];
            #pragma unroll
            for (int j = 0; j < 4; j++) {
                int col = wn * 32 + j * 8 + r;
                bfrag[j][0] = __float_as_uint(Bs[kb + c][col]);
                bfrag[j][1] = __float_as_uint(Bs[kb + c + 4][col]);
            }
            #pragma unroll
            for (int i = 0; i < 4; i++)
                #pragma unroll
                for (int j = 0; j < 4; j++)
                    mma_tf32(acc[i][j], afrag[i], bfrag[j]);
        }
        __syncthreads();
    }

    // Epilogue: bias + optional residual, float2 stores
    #pragma unroll
    for (int i = 0; i < 4; i++) {
        int row0 = m0 + wm * 64 + i * 16 + r;
        #pragma unroll
        for (int j = 0; j < 4; j++) {
            int col = n0 + wn * 32 + j * 8 + 2 * c;
            float bv0 = bias[col];
            float bv1 = bias[col + 1];
            size_t idx0 = (size_t)row0 * N + col;
            size_t idx1 = (size_t)(row0 + 8) * N + col;
            float2 o0, o1;
            o0.x = acc[i][j][0] + bv0; o0.y = acc[i][j][1] + bv1;
            o1.x = acc[i][j][2] + bv0; o1.y = acc[i][j][3] + bv1;
            if (res) {
                const float2 r0 = *(const float2*)(res + idx0);
                const float2 r1 = *(const float2*)(res + idx1);
                o0.x += r0.x; o0.y += r0.y;
                o1.x += r1.x; o1.y += r1.y;
            }
            *(float2*)(C + idx0) = o0;
            *(float2*)(C + idx1) = o1;
        }
    }
}

// ---------------------------------------------------------------------------
// Attention per (sequence n, head h). flat(n,s) = cd*(n/d0) + cm*(n%d0) + cs*s
// rsin/rcos: [S][16] rotary tables (nullptr -> no rotary, lev axis).
// ---------------------------------------------------------------------------
__global__ __launch_bounds__(128) void attn_kernel(
    const float* __restrict__ qkv, float* __restrict__ att,
    const float* __restrict__ rsin, const float* __restrict__ rcos,
    int S, int d0, int cd, int cm, int cs)
{
    __shared__ float k_s[96][33];
    __shared__ float v_s[96][33];
    __shared__ float probs[4][96];

    int n = blockIdx.x;
    int h = blockIdx.y;
    int tid = threadIdx.x;
    int lane = tid & 31;
    int warp = tid >> 5;

    int nb = cd * (n / d0) + cm * (n % d0);
    int qoff = h * HD;
    int koff = DD + h * HD;
    int voff = 2 * DD + h * HD;

    for (int idx = tid; idx < S * 32; idx += 128) {
        int j = idx >> 5;
        int d = idx & 31;
        size_t rowbase = (size_t)(nb + cs * j) * (3 * DD);
        float kv;
        if (rsin) {
            int i = d & 15;
            float sn = rsin[j * 16 + i], cs_ = rcos[j * 16 + i];
            float x1 = qkv[rowbase + koff + 2 * i];
            float x2 = qkv[rowbase + koff + 2 * i + 1];
            kv = (d < 16) ? (x1 * cs_ - x2 * sn) : (x1 * sn + x2 * cs_);
        } else {
            kv = qkv[rowbase + koff + d];
        }
        k_s[j][d] = kv;
        v_s[j][d] = qkv[rowbase + voff + d];
    }
    __syncthreads();

    const float scale = 0.17677669529663687f; // 1/sqrt(32)

    for (int sq = warp; sq < S; sq += 4) {
        size_t qrow = (size_t)(nb + cs * sq) * (3 * DD) + qoff;
        float q[32];
        if (rsin) {
            #pragma unroll
            for (int i = 0; i < 16; i++) {
                float sn = rsin[sq * 16 + i], cs_ = rcos[sq * 16 + i];
                float x1 = qkv[qrow + 2 * i];
                float x2 = qkv[qrow + 2 * i + 1];
                q[i]      = x1 * cs_ - x2 * sn;
                q[16 + i] = x1 * sn + x2 * cs_;
            }
        } else {
            #pragma unroll
            for (int i = 0; i < 32; i++) q[i] = qkv[qrow + i];
        }

        float sc[3];
        float mx = -1e30f;
        #pragma unroll
        for (int kb = 0; kb < 3; kb++) {
            int j = lane + kb * 32;
            float a = 0.f;
            if (j < S) {
                #pragma unroll
                for (int d = 0; d < 32; d++) a += q[d] * k_s[j][d];
                a *= scale;
                mx = fmaxf(mx, a);
            }
            sc[kb] = a;
        }
        #pragma unroll
        for (int o = 16; o; o >>= 1) mx = fmaxf(mx, __shfl_xor_sync(0xffffffffu, mx, o));

        float sum = 0.f;
        #pragma unroll
        for (int kb = 0; kb < 3; kb++) {
            int j = lane + kb * 32;
            if (j < S) {
                float e = expf(sc[kb] - mx);
                probs[warp][j] = e;
                sum += e;
            }
        }
        #pragma unroll
        for (int o = 16; o; o >>= 1) sum += __shfl_xor_sync(0xffffffffu, sum, o);
        float rinv = 1.f / sum;

        __syncwarp();
        float o = 0.f;
        for (int j = 0; j < S; j++) o += probs[warp][j] * v_s[j][lane];
        o *= rinv;
        att[(size_t)(nb + cs * sq) * DD + h * HD + lane] = o;
        __syncwarp();
    }
}

// ---------------------------------------------------------------------------
// Host launcher
// ---------------------------------------------------------------------------
extern "C" void kernel_launch(void* const* d_in, const int* in_sizes, int n_in,
                              void* d_out, int out_size)
{
    const float* x         = (const float*)d_in[0];
    const float* lat_grid  = (const float*)d_in[1];
    const float* lon_grid  = (const float*)d_in[2];
    const float* lat_qkv_w = (const float*)d_in[3];
    const float* lat_qkv_b = (const float*)d_in[4];
    const float* lon_qkv_w = (const float*)d_in[5];
    const float* lon_qkv_b = (const float*)d_in[6];
    const float* lev_qkv_w = (const float*)d_in[7];
    const float* lev_qkv_b = (const float*)d_in[8];
    const float* proj_w    = (const float*)d_in[9];
    const float* proj_b    = (const float*)d_in[10];
    const float* g_lat     = (const float*)d_in[11];
    const float* b_lat     = (const float*)d_in[12];
    const float* g_lon     = (const float*)d_in[13];
    const float* b_lon     = (const float*)d_in[14];
    const float* g_lev     = (const float*)d_in[15];
    const float* b_lev     = (const float*)d_in[16];
    float* out = (float*)d_out;

    float *ln, *qkv, *attb, *state, *slat, *clat, *slon, *clon;
    cudaGetSymbolAddress((void**)&ln,    g_ln);
    cudaGetSymbolAddress((void**)&qkv,   g_qkv);
    cudaGetSymbolAddress((void**)&attb,  g_att);
    cudaGetSymbolAddress((void**)&state, g_state);
    cudaGetSymbolAddress((void**)&slat,  g_sin_lat);
    cudaGetSymbolAddress((void**)&clat,  g_cos_lat);
    cudaGetSymbolAddress((void**)&slon,  g_sin_lon);
    cudaGetSymbolAddress((void**)&clon,  g_cos_lon);

    rotary_kernel<<<(HH * 16 + 127) / 128, 128>>>(lat_grid, HH, 0, slat, clat);
    rotary_kernel<<<(WW * 16 + 127) / 128, 128>>>(lon_grid, WW, 1, slon, clon);

    dim3 gq(3 * DD / 128, TT / 128);   // QKV gemm grid (12, 468)
    dim3 gp(DD / 128, TT / 128);       // proj gemm grid (4, 468)

    // ---- lat block (seq = H, n over (l,w)) ----
    ln_kernel<<<TT, 128>>>(x, g_lat, b_lat, ln);
    gemm_tc_kernel<<<gq, 256>>>(ln, lat_qkv_w, lat_qkv_b, nullptr, qkv, TT, 3 * DD, DD);
    attn_kernel<<<dim3(LL * WW, NHEAD), 128>>>(qkv, attb, slat, clat,
                                               HH, WW, HH * WW, 1, WW);
    gemm_tc_kernel<<<gp, 256>>>(attb, proj_w, proj_b, x, state, TT, DD, DD);

    // ---- lon block (seq = W, n over (l,h)) ----
    ln_kernel<<<TT, 128>>>(state, g_lon, b_lon, ln);
    gemm_tc_kernel<<<gq, 256>>>(ln, lon_qkv_w, lon_qkv_b, nullptr, qkv, TT, 3 * DD, DD);
    attn_kernel<<<dim3(LL * HH, NHEAD), 128>>>(qkv, attb, slon, clon,
                                               WW, 1, WW, 0, 1);
    gemm_tc_kernel<<<gp, 256>>>(attb, proj_w, proj_b, state, state, TT, DD, DD);

    // ---- lev block (seq = L, n over (h,w), no rotary) ----
    ln_kernel<<<TT, 128>>>(state, g_lev, b_lev, ln);
    gemm_tc_kernel<<<gq, 256>>>(ln, lev_qkv_w, lev_qkv_b, nullptr, qkv, TT, 3 * DD, DD);
    attn_kernel<<<dim3(HH * WW, NHEAD), 128>>>(qkv, attb, nullptr, nullptr,
                                               LL, 1, 1, 0, HH * WW);
    gemm_tc_kernel<<<gp, 256>>>(attb, proj_w, proj_b, state, out, TT, DD, DD);
}

// round 4
// speedup vs baseline: 2.0419x; 1.0687x over previous
#include <cuda_runtime.h>
#include <cuda_bf16.h>
#include <math.h>
#include <stdint.h>

// Problem constants
#define LL 13
#define HH 48
#define WW 96
#define DD 512
#define TT (LL*HH*WW)        // 59904 tokens
#define NHEAD 16
#define HD 32

// Scratch (device globals; no cudaMalloc allowed)
__device__ float g_ln[(size_t)TT * DD];
__device__ float g_qkv[(size_t)TT * 3 * DD];
__device__ float g_att[(size_t)TT * DD];
__device__ float g_state[(size_t)TT * DD];
__device__ float g_sin_lat[HH * 16];
__device__ float g_cos_lat[HH * 16];
__device__ float g_sin_lon[WW * 16];
__device__ float g_cos_lon[WW * 16];

// ---------------------------------------------------------------------------
// Rotary sin/cos precompute. mode 0: lat axis (lon=0), mode 1: lon axis (lat=0)
// ---------------------------------------------------------------------------
__global__ void rotary_kernel(const float* __restrict__ grid, int S, int mode,
                              float* __restrict__ sout, float* __restrict__ cout)
{
    int idx = blockIdx.x * blockDim.x + threadIdx.x;
    if (idx >= S * 16) return;
    int s = idx >> 4;
    int f = idx & 15;
    const float PI = 3.14159265358979323846f;
    float lat, lon;
    if (mode == 0) { lat = grid[s]; lon = 0.f; }
    else           { lat = 0.f;     lon = grid[s]; }
    float two_pi = 2.f * PI;
    float r = fmodf(lon + PI, two_pi);
    if (r < 0.f) r += two_pi;
    float lonw = r - PI;
    float lo = -(PI * 0.5f) + 1e-6f;
    float hi =  (PI * 0.5f) - 1e-6f;
    float latc = fminf(fmaxf(lat, lo), hi);
    float invf = powf(10000.f, -(float)f / 16.f);
    float phase = (latc + lonw * cosf(latc)) * invf;
    sout[idx] = sinf(phase);
    cout[idx] = cosf(phase);
}

// ---------------------------------------------------------------------------
// LayerNorm over D=512 per token. 128 threads/block, one block per token.
// ---------------------------------------------------------------------------
__global__ void ln_kernel(const float* __restrict__ x, const float* __restrict__ g,
                          const float* __restrict__ b, float* __restrict__ out)
{
    __shared__ float red[8];
    int t = blockIdx.x;
    int tid = threadIdx.x;
    const float* row = x + (size_t)t * DD;
    float4 v = *(const float4*)(row + tid * 4);
    float s = v.x + v.y + v.z + v.w;
    float q = v.x*v.x + v.y*v.y + v.z*v.z + v.w*v.w;
    #pragma unroll
    for (int o = 16; o; o >>= 1) {
        s += __shfl_xor_sync(0xffffffffu, s, o);
        q += __shfl_xor_sync(0xffffffffu, q, o);
    }
    int lane = tid & 31, w = tid >> 5;
    if (lane == 0) { red[w] = s; red[4 + w] = q; }
    __syncthreads();
    if (tid == 0) {
        red[0] = red[0] + red[1] + red[2] + red[3];
        red[4] = red[4] + red[5] + red[6] + red[7];
    }
    __syncthreads();
    float mean = red[0] * (1.f / 512.f);
    float var  = red[4] * (1.f / 512.f) - mean * mean;
    float inv = rsqrtf(var + 1e-5f);
    float4 gv = *(const float4*)(g + tid * 4);
    float4 bv = *(const float4*)(b + tid * 4);
    float4 o;
    o.x = (v.x - mean) * inv * gv.x + bv.x;
    o.y = (v.y - mean) * inv * gv.y + bv.y;
    o.z = (v.z - mean) * inv * gv.z + bv.z;
    o.w = (v.w - mean) * inv * gv.w + bv.w;
    *(float4*)(out + (size_t)t * DD + tid * 4) = o;
}

// ---------------------------------------------------------------------------
// TF32 tensor-core GEMM: C[M,N] = A[M,K] @ B[K,N] + bias[N] (+ res[M,N])
// Block 128x128, 128 threads = 4 warps (2x2), warp tile 64x64.
// BK=16, cp.async 2-stage double buffer, one __syncthreads per chunk.
// Conflict-free padded smem: As[128][20], Bs[16][136].
// ---------------------------------------------------------------------------
__device__ __forceinline__ void mma_tf32(float* d, const uint32_t* a, const uint32_t* b)
{
    asm volatile(
        "mma.sync.aligned.m16n8k8.row.col.f32.tf32.tf32.f32 "
        "{%0,%1,%2,%3}, {%4,%5,%6,%7}, {%8,%9}, {%0,%1,%2,%3};"
        : "+f"(d[0]), "+f"(d[1]), "+f"(d[2]), "+f"(d[3])
        : "r"(a[0]), "r"(a[1]), "r"(a[2]), "r"(a[3]), "r"(b[0]), "r"(b[1]));
}

__device__ __forceinline__ void cp_async16(uint32_t dst, const void* src)
{
    asm volatile("cp.async.cg.shared.global [%0], [%1], 16;\n" :: "r"(dst), "l"(src));
}

__device__ __forceinline__ void cp_commit()
{
    asm volatile("cp.async.commit_group;\n" ::: "memory");
}

__device__ __forceinline__ void cp_wait0()
{
    asm volatile("cp.async.wait_group 0;\n" ::: "memory");
}

// Issue one chunk's global->shared loads into buffer buf.
__device__ __forceinline__ void gemm_issue_chunk(
    const float* __restrict__ A, const float* __restrict__ B,
    int M, int N, int K, int m0, int n0,
    int ar, int ac, int br, int bc,
    uint32_t as_base, uint32_t bs_base,
    int chunk, int buf)
{
    int k0 = chunk * 16;
    #pragma unroll
    for (int i = 0; i < 4; i++) {
        uint32_t dst = as_base + (uint32_t)(((buf * 128 + ar + 32 * i) * 20 + ac) * 4);
        cp_async16(dst, A + (size_t)(m0 + ar + 32 * i) * K + k0 + ac);
    }
    #pragma unroll
    for (int i = 0; i < 4; i++) {
        uint32_t dst = bs_base + (uint32_t)(((buf * 16 + br + 4 * i) * 136 + bc) * 4);
        cp_async16(dst, B + (size_t)(k0 + br + 4 * i) * N + n0 + bc);
    }
    cp_commit();
}

__global__ __launch_bounds__(128) void gemm_tc_kernel(
    const float* __restrict__ A, const float* __restrict__ B,
    const float* __restrict__ bias, const float* __restrict__ res,
    float* __restrict__ C, int M, int N, int K)
{
    __shared__ float As[2][128][20];
    __shared__ float Bs[2][16][136];

    int tid  = threadIdx.x;
    int lane = tid & 31;
    int warp = tid >> 5;
    int wm   = warp >> 1;     // 0..1 -> 64 rows
    int wn   = warp & 1;      // 0..1 -> 64 cols
    int r    = lane >> 2;     // 0..7
    int c    = lane & 3;      // 0..3

    int m0 = blockIdx.y * 128;
    int n0 = blockIdx.x * 128;

    // Global->shared load mapping (cp.async, 16B each, 8 per thread per chunk)
    int ar = tid >> 2;             // 0..31 (A rows, +32*i)
    int ac = (tid & 3) * 4;        // 0,4,8,12
    int br = tid >> 5;             // 0..3  (B k-rows, +4*i)
    int bc = (tid & 31) * 4;       // B col

    uint32_t as_base = (uint32_t)__cvta_generic_to_shared(&As[0][0][0]);
    uint32_t bs_base = (uint32_t)__cvta_generic_to_shared(&Bs[0][0][0]);

    float acc[4][8][4];
    #pragma unroll
    for (int i = 0; i < 4; i++)
        #pragma unroll
        for (int j = 0; j < 8; j++)
            #pragma unroll
            for (int e = 0; e < 4; e++) acc[i][j][e] = 0.f;

    const int NCHUNK = K / 16;

    gemm_issue_chunk(A, B, M, N, K, m0, n0, ar, ac, br, bc, as_base, bs_base, 0, 0);

    for (int chunk = 0; chunk < NCHUNK; chunk++) {
        int buf = chunk & 1;
        cp_wait0();
        __syncthreads();

        if (chunk + 1 < NCHUNK)
            gemm_issue_chunk(A, B, M, N, K, m0, n0, ar, ac, br, bc,
                             as_base, bs_base, chunk + 1, buf ^ 1);

        #pragma unroll
        for (int ks = 0; ks < 2; ks++) {
            int kb = ks * 8;
            uint32_t afrag[4][4];
            #pragma unroll
            for (int i = 0; i < 4; i++) {
                int row = wm * 64 + i * 16 + r;
                afrag[i][0] = __float_as_uint(As[buf][row][kb + c]);
                afrag[i][1] = __float_as_uint(As[buf][row + 8][kb + c]);
                afrag[i][2] = __float_as_uint(As[buf][row][kb + c + 4]);
                afrag[i][3] = __float_as_uint(As[buf][row + 8][kb + c + 4]);
            }
            uint32_t bfrag[8][2];
            #pragma unroll
            for (int j = 0; j < 8; j++) {
                int col = wn * 64 + j * 8 + r;
                bfrag[j][0] = __float_as_uint(Bs[buf][kb + c][col]);
                bfrag[j][1] = __float_as_uint(Bs[buf][kb + c + 4][col]);
            }
            #pragma unroll
            for (int i = 0; i < 4; i++)
                #pragma unroll
                for (int j = 0; j < 8; j++)
                    mma_tf32(acc[i][j], afrag[i], bfrag[j]);
        }
        __syncthreads();
    }

    // Epilogue: bias + optional residual
    #pragma unroll
    for (int i = 0; i < 4; i++) {
        int row0 = m0 + wm * 64 + i * 16 + r;
        #pragma unroll
        for (int j = 0; j < 8; j++) {
            int col = n0 + wn * 64 + j * 8 + 2 * c;
            float bv0 = bias[col];
            float bv1 = bias[col + 1];
            size_t idx0 = (size_t)row0 * N + col;
            size_t idx1 = (size_t)(row0 + 8) * N + col;
            float2 o0, o1;
            o0.x = acc[i][j][0] + bv0; o0.y = acc[i][j][1] + bv1;
            o1.x = acc[i][j][2] + bv0; o1.y = acc[i][j][3] + bv1;
            if (res) {
                const float2 r0 = *(const float2*)(res + idx0);
                const float2 r1 = *(const float2*)(res + idx1);
                o0.x += r0.x; o0.y += r0.y;
                o1.x += r1.x; o1.y += r1.y;
            }
            *(float2*)(C + idx0) = o0;
            *(float2*)(C + idx1) = o1;
        }
    }
}

// ---------------------------------------------------------------------------
// Attention per (sequence n, head h). flat(n,s) = cd*(n/d0) + cm*(n%d0) + cs*s
// rsin/rcos: [S][16] rotary tables (nullptr -> no rotary, lev axis).
// ---------------------------------------------------------------------------
__global__ __launch_bounds__(128) void attn_kernel(
    const float* __restrict__ qkv, float* __restrict__ att,
    const float* __restrict__ rsin, const float* __restrict__ rcos,
    int S, int d0, int cd, int cm, int cs)
{
    __shared__ float k_s[96][33];
    __shared__ float v_s[96][33];
    __shared__ float probs[4][96];

    int n = blockIdx.x;
    int h = blockIdx.y;
    int tid = threadIdx.x;
    int lane = tid & 31;
    int warp = tid >> 5;

    int nb = cd * (n / d0) + cm * (n % d0);
    int qoff = h * HD;
    int koff = DD + h * HD;
    int voff = 2 * DD + h * HD;

    for (int idx = tid; idx < S * 32; idx += 128) {
        int j = idx >> 5;
        int d = idx & 31;
        size_t rowbase = (size_t)(nb + cs * j) * (3 * DD);
        float kv;
        if (rsin) {
            int i = d & 15;
            float sn = rsin[j * 16 + i], cs_ = rcos[j * 16 + i];
            float x1 = qkv[rowbase + koff + 2 * i];
            float x2 = qkv[rowbase + koff + 2 * i + 1];
            kv = (d < 16) ? (x1 * cs_ - x2 * sn) : (x1 * sn + x2 * cs_);
        } else {
            kv = qkv[rowbase + koff + d];
        }
        k_s[j][d] = kv;
        v_s[j][d] = qkv[rowbase + voff + d];
    }
    __syncthreads();

    const float scale = 0.17677669529663687f; // 1/sqrt(32)

    for (int sq = warp; sq < S; sq += 4) {
        size_t qrow = (size_t)(nb + cs * sq) * (3 * DD) + qoff;
        float q[32];
        if (rsin) {
            #pragma unroll
            for (int i = 0; i < 16; i++) {
                float sn = rsin[sq * 16 + i], cs_ = rcos[sq * 16 + i];
                float x1 = qkv[qrow + 2 * i];
                float x2 = qkv[qrow + 2 * i + 1];
                q[i]      = x1 * cs_ - x2 * sn;
                q[16 + i] = x1 * sn + x2 * cs_;
            }
        } else {
            #pragma unroll
            for (int i = 0; i < 32; i++) q[i] = qkv[qrow + i];
        }

        float sc[3];
        float mx = -1e30f;
        #pragma unroll
        for (int kb = 0; kb < 3; kb++) {
            int j = lane + kb * 32;
            float a = 0.f;
            if (j < S) {
                #pragma unroll
                for (int d = 0; d < 32; d++) a += q[d] * k_s[j][d];
                a *= scale;
                mx = fmaxf(mx, a);
            }
            sc[kb] = a;
        }
        #pragma unroll
        for (int o = 16; o; o >>= 1) mx = fmaxf(mx, __shfl_xor_sync(0xffffffffu, mx, o));

        float sum = 0.f;
        #pragma unroll
        for (int kb = 0; kb < 3; kb++) {
            int j = lane + kb * 32;
            if (j < S) {
                float e = expf(sc[kb] - mx);
                probs[warp][j] = e;
                sum += e;
            }
        }
        #pragma unroll
        for (int o = 16; o; o >>= 1) sum += __shfl_xor_sync(0xffffffffu, sum, o);
        float rinv = 1.f / sum;

        __syncwarp();
        float o = 0.f;
        for (int j = 0; j < S; j++) o += probs[warp][j] * v_s[j][lane];
        o *= rinv;
        att[(size_t)(nb + cs * sq) * DD + h * HD + lane] = o;
        __syncwarp();
    }
}

// ---------------------------------------------------------------------------
// Host launcher
// ---------------------------------------------------------------------------
extern "C" void kernel_launch(void* const* d_in, const int* in_sizes, int n_in,
                              void* d_out, int out_size)
{
    const float* x         = (const float*)d_in[0];
    const float* lat_grid  = (const float*)d_in[1];
    const float* lon_grid  = (const float*)d_in[2];
    const float* lat_qkv_w = (const float*)d_in[3];
    const float* lat_qkv_b = (const float*)d_in[4];
    const float* lon_qkv_w = (const float*)d_in[5];
    const float* lon_qkv_b = (const float*)d_in[6];
    const float* lev_qkv_w = (const float*)d_in[7];
    const float* lev_qkv_b = (const float*)d_in[8];
    const float* proj_w    = (const float*)d_in[9];
    const float* proj_b    = (const float*)d_in[10];
    const float* g_lat     = (const float*)d_in[11];
    const float* b_lat     = (const float*)d_in[12];
    const float* g_lon     = (const float*)d_in[13];
    const float* b_lon     = (const float*)d_in[14];
    const float* g_lev     = (const float*)d_in[15];
    const float* b_lev     = (const float*)d_in[16];
    float* out = (float*)d_out;

    float *ln, *qkv, *attb, *state, *slat, *clat, *slon, *clon;
    cudaGetSymbolAddress((void**)&ln,    g_ln);
    cudaGetSymbolAddress((void**)&qkv,   g_qkv);
    cudaGetSymbolAddress((void**)&attb,  g_att);
    cudaGetSymbolAddress((void**)&state, g_state);
    cudaGetSymbolAddress((void**)&slat,  g_sin_lat);
    cudaGetSymbolAddress((void**)&clat,  g_cos_lat);
    cudaGetSymbolAddress((void**)&slon,  g_sin_lon);
    cudaGetSymbolAddress((void**)&clon,  g_cos_lon);

    rotary_kernel<<<(HH * 16 + 127) / 128, 128>>>(lat_grid, HH, 0, slat, clat);
    rotary_kernel<<<(WW * 16 + 127) / 128, 128>>>(lon_grid, WW, 1, slon, clon);

    dim3 gq(3 * DD / 128, TT / 128);   // QKV gemm grid (12, 468)
    dim3 gp(DD / 128, TT / 128);       // proj gemm grid (4, 468)

    // ---- lat block (seq = H, n over (l,w)) ----
    ln_kernel<<<TT, 128>>>(x, g_lat, b_lat, ln);
    gemm_tc_kernel<<<gq, 128>>>(ln, lat_qkv_w, lat_qkv_b, nullptr, qkv, TT, 3 * DD, DD);
    attn_kernel<<<dim3(LL * WW, NHEAD), 128>>>(qkv, attb, slat, clat,
                                               HH, WW, HH * WW, 1, WW);
    gemm_tc_kernel<<<gp, 128>>>(attb, proj_w, proj_b, x, state, TT, DD, DD);

    // ---- lon block (seq = W, n over (l,h)) ----
    ln_kernel<<<TT, 128>>>(state, g_lon, b_lon, ln);
    gemm_tc_kernel<<<gq, 128>>>(ln, lon_qkv_w, lon_qkv_b, nullptr, qkv, TT, 3 * DD, DD);
    attn_kernel<<<dim3(LL * HH, NHEAD), 128>>>(qkv, attb, slon, clon,
                                               WW, 1, WW, 0, 1);
    gemm_tc_kernel<<<gp, 128>>>(attb, proj_w, proj_b, state, state, TT, DD, DD);

    // ---- lev block (seq = L, n over (h,w), no rotary) ----
    ln_kernel<<<TT, 128>>>(state, g_lev, b_lev, ln);
    gemm_tc_kernel<<<gq, 128>>>(ln, lev_qkv_w, lev_qkv_b, nullptr, qkv, TT, 3 * DD, DD);
    attn_kernel<<<dim3(HH * WW, NHEAD), 128>>>(qkv, attb, nullptr, nullptr,
                                               LL, 1, 1, 0, HH * WW);
    gemm_tc_kernel<<<gp, 128>>>(attb, proj_w, proj_b, state, out, TT, DD, DD);
}